// round 1
// baseline (speedup 1.0000x reference)
#include <cuda_runtime.h>

// Problem constants
#define B_      256
#define L_      2048
#define V_      8
#define NS_     5        // shapelets
#define BAG_    409
#define SHIFT_  204
#define NB_     9        // windows
#define FEAT_   80       // 2*NS*V
#define NCLASS_ 10
#define BN_EPS_ 1e-5f

// Scratch for feature matrix [B, FEAT]
__device__ float g_feat[B_ * FEAT_];

// ---------------------------------------------------------------------------
// Kernel 1: per-(b,v) warp computes 5x9 L2 distances via the expansion
//   ||x - s||^2 = sum(x^2) + sum(s^2) - 2*sum(x*s)
// then min/mean over the 9 windows -> feat[b, :].
// ---------------------------------------------------------------------------
__global__ __launch_bounds__(256, 2)
void shapelet_feat_kernel(const float* __restrict__ x,
                          const float* __restrict__ shp,
                          float* __restrict__ feat)
{
    const int warp = threadIdx.x >> 5;
    const int lane = threadIdx.x & 31;
    const int g = blockIdx.x * 8 + warp;          // global warp id in [0, 2048)
    const int b = g >> 3;
    const int v = g & 7;

    const float* __restrict__ xr = x + (size_t)b * (V_ * L_) + (size_t)v * L_;
    // shapelet[s, v, t] = shp[s*V*BAG + v*BAG + t]
    const float* __restrict__ sv_base = shp + (size_t)v * BAG_;

    float c[NS_][NB_];
    float sx2[NB_];
    float ss2[NS_];
#pragma unroll
    for (int s = 0; s < NS_; s++) {
        ss2[s] = 0.f;
#pragma unroll
        for (int nb = 0; nb < NB_; nb++) c[s][nb] = 0.f;
    }
#pragma unroll
    for (int nb = 0; nb < NB_; nb++) sx2[nb] = 0.f;

    // 409 = 12*32 + 25
    for (int k = 0; k < 13; k++) {
        const int t = lane + (k << 5);
        const bool ok = (t < BAG_);

        float xv[NB_];
#pragma unroll
        for (int nb = 0; nb < NB_; nb++)
            xv[nb] = ok ? xr[nb * SHIFT_ + t] : 0.f;

        float sw[NS_];
#pragma unroll
        for (int s = 0; s < NS_; s++)
            sw[s] = ok ? sv_base[s * (V_ * BAG_) + t] : 0.f;

#pragma unroll
        for (int nb = 0; nb < NB_; nb++)
            sx2[nb] = fmaf(xv[nb], xv[nb], sx2[nb]);
#pragma unroll
        for (int s = 0; s < NS_; s++)
            ss2[s] = fmaf(sw[s], sw[s], ss2[s]);
#pragma unroll
        for (int s = 0; s < NS_; s++)
#pragma unroll
            for (int nb = 0; nb < NB_; nb++)
                c[s][nb] = fmaf(xv[nb], sw[s], c[s][nb]);
    }

    // Butterfly reduce all 59 accumulators across the warp
#pragma unroll
    for (int off = 16; off > 0; off >>= 1) {
#pragma unroll
        for (int nb = 0; nb < NB_; nb++)
            sx2[nb] += __shfl_xor_sync(0xffffffffu, sx2[nb], off);
#pragma unroll
        for (int s = 0; s < NS_; s++)
            ss2[s] += __shfl_xor_sync(0xffffffffu, ss2[s], off);
#pragma unroll
        for (int s = 0; s < NS_; s++)
#pragma unroll
            for (int nb = 0; nb < NB_; nb++)
                c[s][nb] += __shfl_xor_sync(0xffffffffu, c[s][nb], off);
    }

    if (lane == 0) {
        float* fout = feat + (size_t)b * FEAT_;
#pragma unroll
        for (int s = 0; s < NS_; s++) {
            float dmin = 3.402823466e+38f;
            float dsum = 0.f;
#pragma unroll
            for (int nb = 0; nb < NB_; nb++) {
                float d2 = sx2[nb] + ss2[s] - 2.f * c[s][nb];
                float d = sqrtf(fmaxf(d2, 0.f));
                dmin = fminf(dmin, d);
                dsum += d;
            }
            fout[s * V_ + v]          = dmin;
            fout[NS_ * V_ + s * V_ + v] = dsum * (1.f / 9.f);
        }
    }
}

// ---------------------------------------------------------------------------
// Kernel 2: BatchNorm (training-mode batch stats, two-pass variance) folded
// into the FC layer. Single block of 256 threads; feat staged in smem with
// stride 81 (conflict-free FC reads).
// ---------------------------------------------------------------------------
#define FSTRIDE_ 81
#define SMEM2_BYTES_ (B_ * FSTRIDE_ * sizeof(float))

__global__ void bn_fc_kernel(const float* __restrict__ feat,
                             const float* __restrict__ gamma,
                             const float* __restrict__ beta,
                             const float* __restrict__ w,
                             const float* __restrict__ fb,
                             float* __restrict__ out)
{
    extern __shared__ float sf[];            // [B_][FSTRIDE_]
    __shared__ float s_scale[FEAT_];         // gamma * rstd
    __shared__ float s_shift[FEAT_];         // beta - mu * scale
    __shared__ float s_wp[NCLASS_ * FEAT_];  // w * scale
    __shared__ float s_bias[NCLASS_];

    const int tid = threadIdx.x;

    // stage feature matrix
    for (int i = tid; i < B_ * FEAT_; i += 256) {
        int bb = i / FEAT_;
        int f  = i - bb * FEAT_;
        sf[bb * FSTRIDE_ + f] = feat[i];
    }
    __syncthreads();

    // per-feature batch stats (two-pass for accuracy)
    if (tid < FEAT_) {
        const int f = tid;
        float s0 = 0.f, s1 = 0.f, s2 = 0.f, s3 = 0.f;
        for (int bb = 0; bb < B_; bb += 4) {
            s0 += sf[(bb + 0) * FSTRIDE_ + f];
            s1 += sf[(bb + 1) * FSTRIDE_ + f];
            s2 += sf[(bb + 2) * FSTRIDE_ + f];
            s3 += sf[(bb + 3) * FSTRIDE_ + f];
        }
        const float mu = (s0 + s1 + s2 + s3) * (1.f / 256.f);
        float v0 = 0.f, v1 = 0.f, v2 = 0.f, v3 = 0.f;
        for (int bb = 0; bb < B_; bb += 4) {
            float d0 = sf[(bb + 0) * FSTRIDE_ + f] - mu;
            float d1 = sf[(bb + 1) * FSTRIDE_ + f] - mu;
            float d2 = sf[(bb + 2) * FSTRIDE_ + f] - mu;
            float d3 = sf[(bb + 3) * FSTRIDE_ + f] - mu;
            v0 = fmaf(d0, d0, v0);
            v1 = fmaf(d1, d1, v1);
            v2 = fmaf(d2, d2, v2);
            v3 = fmaf(d3, d3, v3);
        }
        const float var = (v0 + v1 + v2 + v3) * (1.f / 256.f);
        const float rstd = rsqrtf(var + BN_EPS_);
        const float scale = gamma[f] * rstd;
        s_scale[f] = scale;
        s_shift[f] = beta[f] - mu * scale;
    }
    __syncthreads();

    // fold BN into FC weights
    for (int i = tid; i < NCLASS_ * FEAT_; i += 256) {
        int f = i % FEAT_;
        s_wp[i] = w[i] * s_scale[f];
    }
    __syncthreads();
    if (tid < NCLASS_) {
        float a = fb[tid];
        for (int f = 0; f < FEAT_; f++)
            a = fmaf(s_shift[f], w[tid * FEAT_ + f], a);
        s_bias[tid] = a;
    }
    __syncthreads();

    // FC: one thread per batch row, feature row in registers
    {
        const int bb = tid;  // 256 threads == 256 rows
        float r[FEAT_];
#pragma unroll
        for (int f = 0; f < FEAT_; f++)
            r[f] = sf[bb * FSTRIDE_ + f];
#pragma unroll
        for (int cc = 0; cc < NCLASS_; cc++) {
            float a = s_bias[cc];
#pragma unroll
            for (int f = 0; f < FEAT_; f++)
                a = fmaf(r[f], s_wp[cc * FEAT_ + f], a);
            out[bb * NCLASS_ + cc] = a;
        }
    }
}

// ---------------------------------------------------------------------------
extern "C" void kernel_launch(void* const* d_in, const int* in_sizes, int n_in,
                              void* d_out, int out_size)
{
    const float* x     = (const float*)d_in[0];  // [256, 2048, 8]
    const float* shp   = (const float*)d_in[1];  // [1, 5, 8, 409, 1]
    const float* gamma = (const float*)d_in[2];  // [80]
    const float* beta  = (const float*)d_in[3];  // [80]
    const float* fcw   = (const float*)d_in[4];  // [10, 80]
    const float* fcb   = (const float*)d_in[5];  // [10]
    float* out = (float*)d_out;                  // [256, 10]

    static bool attr_set = false;
    if (!attr_set) {
        cudaFuncSetAttribute(bn_fc_kernel,
                             cudaFuncAttributeMaxDynamicSharedMemorySize,
                             (int)SMEM2_BYTES_);
        attr_set = true;
    }

    float* feat = nullptr;
    cudaGetSymbolAddress((void**)&feat, g_feat);

    shapelet_feat_kernel<<<256, 256>>>(x, shp, feat);
    bn_fc_kernel<<<1, 256, SMEM2_BYTES_>>>(feat, gamma, beta, fcw, fcb, out);
}